// round 2
// baseline (speedup 1.0000x reference)
#include <cuda_runtime.h>
#include <cuda_bf16.h>
#include <cstdint>

// Problem constants
#define Bb   4
#define Tt   512
#define Uu   96
#define Ff   512
#define Hh   512
#define Vv   256
#define UP1  97      // U+1 lattice rows
#define VP1  257     // V+1 vocab (incl. blank)
#define NPAD 264     // VP1 padded to 33 n-tiles of 8
#define NEG_INFF (-1e30f)

// ---------------- device scratch (no allocations allowed) ----------------
__device__ float          g_fproj[Bb * Tt * Hh];     // 4 MB
__device__ __nv_bfloat16  g_Wo[Hh * NPAD];           // 270 KB, padded bf16 Wo
__device__ float          g_blank[Bb * Tt * UP1];    // ~0.8 MB
__device__ float          g_lex[Bb * Tt * Uu];       // ~0.8 MB

// ---------------- kernel 1: fproj = frames @ Wf (fp32 tiled) -------------
__global__ __launch_bounds__(256) void fproj_kernel(
    const float* __restrict__ frames, const float* __restrict__ Wf)
{
    __shared__ float sF[64][36];  // [row][k], padded stride
    __shared__ float sW[32][68];  // [k][col], padded stride
    const int row0 = blockIdx.x * 64;
    const int col0 = blockIdx.y * 64;
    const int tid = threadIdx.x;
    const int tx = tid & 15, ty = tid >> 4;

    float acc[4][4];
#pragma unroll
    for (int i = 0; i < 4; i++)
#pragma unroll
        for (int j = 0; j < 4; j++) acc[i][j] = 0.f;

    for (int k0 = 0; k0 < Ff; k0 += 32) {
        __syncthreads();
#pragma unroll
        for (int i = 0; i < 8; i++) {          // 64*32 = 2048 elems
            int idx = tid + i * 256;
            int r = idx >> 5, k = idx & 31;
            sF[r][k] = frames[(size_t)(row0 + r) * Ff + k0 + k];
        }
#pragma unroll
        for (int i = 0; i < 8; i++) {          // 32*64 = 2048 elems
            int idx = tid + i * 256;
            int k = idx >> 6, c = idx & 63;
            sW[k][c] = Wf[(size_t)(k0 + k) * Hh + col0 + c];
        }
        __syncthreads();
#pragma unroll
        for (int k = 0; k < 32; k++) {
            float a_[4], b_[4];
#pragma unroll
            for (int i = 0; i < 4; i++) a_[i] = sF[ty * 4 + i][k];
#pragma unroll
            for (int j = 0; j < 4; j++) b_[j] = sW[k][tx * 4 + j];
#pragma unroll
            for (int i = 0; i < 4; i++)
#pragma unroll
                for (int j = 0; j < 4; j++) acc[i][j] += a_[i] * b_[j];
        }
    }
#pragma unroll
    for (int i = 0; i < 4; i++)
#pragma unroll
        for (int j = 0; j < 4; j++)
            g_fproj[(size_t)(row0 + ty * 4 + i) * Hh + col0 + tx * 4 + j] = acc[i][j];
}

// ---------------- kernel 2: Wo -> bf16, padded to NPAD cols --------------
__global__ void woprep_kernel(const float* __restrict__ Wo)
{
    int i = blockIdx.x * blockDim.x + threadIdx.x;
    if (i >= Hh * NPAD) return;
    int k = i / NPAD, n = i - k * NPAD;
    float v = (n < VP1) ? Wo[(size_t)k * VP1 + n] : 0.f;
    g_Wo[i] = __float2bfloat16(v);
}

// ---------------- kernel 3: fused joint + log-softmax --------------------
// One CTA per (b,t). M = 112 rows (u padded), N = 264 (v padded), K = 512.
// bf16 mma.sync.m16n8k16, fp32 accum in registers.

#define SMEMB_BYTES 120832   // 2560 header + max(loop 50.9KB, logits 115.5KB)

__device__ __forceinline__ void mma16816(
    float c[4], uint32_t a0, uint32_t a1, uint32_t a2, uint32_t a3,
    uint32_t b0, uint32_t b1)
{
    asm volatile(
        "mma.sync.aligned.m16n8k16.row.col.f32.bf16.bf16.f32 "
        "{%0,%1,%2,%3}, {%4,%5,%6,%7}, {%8,%9}, {%0,%1,%2,%3};\n"
        : "+f"(c[0]), "+f"(c[1]), "+f"(c[2]), "+f"(c[3])
        : "r"(a0), "r"(a1), "r"(a2), "r"(a3), "r"(b0), "r"(b1));
}

__global__ __launch_bounds__(512, 1) void joint_kernel(
    const int* __restrict__ labels, const float* __restrict__ E)
{
    extern __shared__ unsigned char smem[];
    float*          fprow = (float*)smem;                         // 512 f32
    int*            cctx  = (int*)(smem + 2048);                  // 112 i32
    __nv_bfloat16*  sA    = (__nv_bfloat16*)(smem + 2560);        // 112 x 72
    __nv_bfloat16*  sB    = (__nv_bfloat16*)(smem + 2560 + 112 * 72 * 2); // 64 x 272
    float*          slog  = (float*)(smem + 2560);                // 112 x 264 (epilogue union)

    const int bt = blockIdx.x;
    const int b  = bt >> 9;
    const int tid = threadIdx.x;
    const int lane = tid & 31, warp = tid >> 5;
    const int gid = lane >> 2, qid = lane & 3;

    // per-(b,t) header
    fprow[tid & 511] = g_fproj[(size_t)bt * Hh + (tid & 511)];
    if (tid < 112) {
        int u = tid, c = 0;
        if (u >= 1 && u <= Uu) c = labels[b * Uu + (u - 1)];
        cctx[tid] = c;
    }
    __syncthreads();

    float C[7][3][4];
#pragma unroll
    for (int m = 0; m < 7; m++)
#pragma unroll
        for (int j = 0; j < 3; j++)
#pragma unroll
            for (int q = 0; q < 4; q++) C[m][j][q] = 0.f;

    for (int kt = 0; kt < 8; kt++) {
        const int k0 = kt * 64;
        // ---- build A tile: h = tanh(fproj + cemb), bf16 ----
#pragma unroll
        for (int i = 0; i < 14; i++) {            // 112*64 / 512
            int idx = tid + i * 512;
            int r = idx >> 6, k = idx & 63;
            float v = 0.f;
            if (r < UP1) {
                float x = fprow[k0 + k] + E[(size_t)cctx[r] * Hh + k0 + k];
                asm("tanh.approx.f32 %0, %1;" : "=f"(v) : "f"(x));
            }
            sA[r * 72 + k] = __float2bfloat16(v);
        }
        // ---- load B tile (Wo k-slab), 32-bit copies ----
        {
            const uint32_t* src = (const uint32_t*)(g_Wo + (size_t)k0 * NPAD);
            uint32_t* dst = (uint32_t*)sB;
            for (int idx = tid; idx < 64 * 132; idx += 512) {
                int k = idx / 132, n2 = idx - k * 132;
                dst[k * 136 + n2] = src[idx];
            }
        }
        __syncthreads();

#pragma unroll
        for (int kk = 0; kk < 4; kk++) {
            const int kb = kk * 16;
            uint32_t Bf[3][2];
#pragma unroll
            for (int j = 0; j < 3; j++) { Bf[j][0] = 0u; Bf[j][1] = 0u; }
#pragma unroll
            for (int j = 0; j < 3; j++) {
                int nt = warp + 16 * j;
                if (nt < 33) {
                    int n = nt * 8 + gid;
                    int kr = kb + qid * 2;
                    const unsigned short* p = (const unsigned short*)sB;
                    uint32_t lo0 = p[kr * 272 + n];
                    uint32_t hi0 = p[(kr + 1) * 272 + n];
                    uint32_t lo1 = p[(kr + 8) * 272 + n];
                    uint32_t hi1 = p[(kr + 9) * 272 + n];
                    Bf[j][0] = lo0 | (hi0 << 16);
                    Bf[j][1] = lo1 | (hi1 << 16);
                }
            }
#pragma unroll
            for (int mt = 0; mt < 7; mt++) {
                const uint32_t* pa = (const uint32_t*)sA;   // 36 u32 per row
                int r0 = mt * 16 + gid;
                uint32_t a0 = pa[r0 * 36 + (kb >> 1) + qid];
                uint32_t a1 = pa[(r0 + 8) * 36 + (kb >> 1) + qid];
                uint32_t a2 = pa[r0 * 36 + (kb >> 1) + 4 + qid];
                uint32_t a3 = pa[(r0 + 8) * 36 + (kb >> 1) + 4 + qid];
#pragma unroll
                for (int j = 0; j < 3; j++)
                    if (warp + 16 * j < 33)
                        mma16816(C[mt][j], a0, a1, a2, a3, Bf[j][0], Bf[j][1]);
            }
        }
        __syncthreads();
    }

    // ---- epilogue: registers -> smem logits ----
#pragma unroll
    for (int mt = 0; mt < 7; mt++)
#pragma unroll
        for (int j = 0; j < 3; j++) {
            int nt = warp + 16 * j;
            if (nt < 33) {
                int r = mt * 16 + gid, c = nt * 8 + qid * 2;
                *(float2*)&slog[r * NPAD + c]        = make_float2(C[mt][j][0], C[mt][j][1]);
                *(float2*)&slog[(r + 8) * NPAD + c]  = make_float2(C[mt][j][2], C[mt][j][3]);
            }
        }
    __syncthreads();

    // ---- per-row LSE; logits are tiny (|x|<~2) so no max-shift needed ----
    for (int r = warp; r < UP1; r += 16) {
        float s = 0.f;
        for (int c = lane; c < VP1; c += 32)
            s += __expf(slog[r * NPAD + c]);
#pragma unroll
        for (int o = 16; o; o >>= 1) s += __shfl_xor_sync(0xffffffffu, s, o);
        float lse = __logf(s);
        if (lane == 0) {
            g_blank[(size_t)bt * UP1 + r] = slog[r * NPAD] - lse;
            if (r < Uu) {
                int lab = labels[b * Uu + r];   // 1..V
                g_lex[(size_t)bt * Uu + r] = slog[r * NPAD + lab] - lse;
            }
        }
    }
}

// ---------------- kernel 4: forward DP (log semiring) --------------------
__global__ __launch_bounds__(128) void dp_kernel(
    const int* __restrict__ num_frames, const int* __restrict__ num_labels,
    float* __restrict__ out)
{
    __shared__ float alpha[UP1];
    const int b = blockIdx.x;
    const int tid = threadIdx.x;
    const int u = tid;
    const bool act = (u < UP1);
    if (act) alpha[u] = (u == 0) ? 0.f : NEG_INFF;
    const int nf = num_frames[b];
    const int nl = num_labels[b];
    __syncthreads();

    const float* bl_ptr = g_blank + (size_t)b * Tt * UP1;
    const float* lx_ptr = g_lex + (size_t)b * Tt * Uu;

    float bl = act ? bl_ptr[u] : 0.f;
    float lx = (act && u >= 1) ? lx_ptr[u - 1] : NEG_INFF;

    for (int t = 0; t < Tt; t++) {
        // software prefetch next step's arc weights
        float bln = 0.f, lxn = NEG_INFF;
        if (t + 1 < Tt) {
            if (act) bln = bl_ptr[(size_t)(t + 1) * UP1 + u];
            if (act && u >= 1) lxn = lx_ptr[(size_t)(t + 1) * Uu + (u - 1)];
        }
        float nv = NEG_INFF;
        if (act) {
            float stay = alpha[u] + bl;
            float emit = (u >= 1) ? alpha[u - 1] + lx : NEG_INFF;
            float m = fmaxf(stay, emit);
            nv = (m < -1e29f) ? NEG_INFF
                              : m + log1pf(__expf(fminf(stay, emit) - m));
        }
        __syncthreads();                 // all reads of alpha done
        if (act && t < nf) alpha[u] = nv;
        __syncthreads();                 // writes visible
        bl = bln; lx = lxn;
    }
    if (tid == 0) out[b] = -alpha[nl];
}

// ---------------- launch ------------------------------------------------
extern "C" void kernel_launch(void* const* d_in, const int* in_sizes, int n_in,
                              void* d_out, int out_size)
{
    const float* frames     = (const float*)d_in[0];
    const int*   num_frames = (const int*)  d_in[1];
    const int*   labels     = (const int*)  d_in[2];
    const int*   num_labels = (const int*)  d_in[3];
    const float* Wf         = (const float*)d_in[4];
    const float* E          = (const float*)d_in[5];
    const float* Wo         = (const float*)d_in[6];
    float* out = (float*)d_out;

    cudaFuncSetAttribute(joint_kernel,
                         cudaFuncAttributeMaxDynamicSharedMemorySize, SMEMB_BYTES);

    fproj_kernel<<<dim3(Bb * Tt / 64, Hh / 64), 256>>>(frames, Wf);
    woprep_kernel<<<(Hh * NPAD + 255) / 256, 256>>>(Wo);
    joint_kernel<<<Bb * Tt, 512, SMEMB_BYTES>>>(labels, E);
    dp_kernel<<<Bb, 128>>>(num_frames, num_labels, out);
}

// round 3
// speedup vs baseline: 1.3465x; 1.3465x over previous
#include <cuda_runtime.h>
#include <cuda_bf16.h>
#include <cstdint>

// Problem constants
#define Bb   4
#define Tt   512
#define Uu   96
#define Ff   512
#define Hh   512
#define Vv   256
#define UP1  97      // U+1 lattice rows
#define VP1  257     // V+1 vocab (incl. blank)
#define NPAD 264     // VP1 padded to 33 n-tiles of 8
#define MPAD 128     // 112 rows padded to 8 m-tiles of 16
#define NEG_INFF (-1e30f)

// ---------------- device scratch ----------------
__device__ float          g_fproj[Bb * Tt * Hh];     // 4 MB
__device__ __nv_bfloat16  g_WoT[NPAD * Hh];          // Wo transposed: [n][k]
__device__ float          g_blank[Bb * Tt * UP1];
__device__ float          g_lex[Bb * Tt * Uu];

// ---------------- kernel 1: fproj = frames @ Wf (fp32 tiled) -------------
__global__ __launch_bounds__(256) void fproj_kernel(
    const float* __restrict__ frames, const float* __restrict__ Wf)
{
    __shared__ float sF[64][36];
    __shared__ float sW[32][68];
    const int row0 = blockIdx.x * 64;
    const int col0 = blockIdx.y * 64;
    const int tid = threadIdx.x;
    const int tx = tid & 15, ty = tid >> 4;

    float acc[4][4];
#pragma unroll
    for (int i = 0; i < 4; i++)
#pragma unroll
        for (int j = 0; j < 4; j++) acc[i][j] = 0.f;

    for (int k0 = 0; k0 < Ff; k0 += 32) {
        __syncthreads();
#pragma unroll
        for (int i = 0; i < 8; i++) {
            int idx = tid + i * 256;
            int r = idx >> 5, k = idx & 31;
            sF[r][k] = frames[(size_t)(row0 + r) * Ff + k0 + k];
        }
#pragma unroll
        for (int i = 0; i < 8; i++) {
            int idx = tid + i * 256;
            int k = idx >> 6, c = idx & 63;
            sW[k][c] = Wf[(size_t)(k0 + k) * Hh + col0 + c];
        }
        __syncthreads();
#pragma unroll
        for (int k = 0; k < 32; k++) {
            float a_[4], b_[4];
#pragma unroll
            for (int i = 0; i < 4; i++) a_[i] = sF[ty * 4 + i][k];
#pragma unroll
            for (int j = 0; j < 4; j++) b_[j] = sW[k][tx * 4 + j];
#pragma unroll
            for (int i = 0; i < 4; i++)
#pragma unroll
                for (int j = 0; j < 4; j++) acc[i][j] += a_[i] * b_[j];
        }
    }
#pragma unroll
    for (int i = 0; i < 4; i++)
#pragma unroll
        for (int j = 0; j < 4; j++)
            g_fproj[(size_t)(row0 + ty * 4 + i) * Hh + col0 + tx * 4 + j] = acc[i][j];
}

// ---------------- kernel 2: Wo -> bf16 transposed [n][k] ------------------
__global__ void woprep_kernel(const float* __restrict__ Wo)
{
    int i = blockIdx.x * blockDim.x + threadIdx.x;
    if (i < Hh * VP1) {
        int k = i / VP1, n = i - k * VP1;   // coalesced read of Wo
        g_WoT[(size_t)n * Hh + k] = __float2bfloat16(Wo[i]);
    }
    if (i < (NPAD - VP1) * Hh) {            // zero-pad rows 257..263
        int n = VP1 + i / Hh, k = i - (i / Hh) * Hh;
        g_WoT[(size_t)n * Hh + k] = __float2bfloat16(0.f);
    }
}

// ---------------- kernel 3: fused joint + log-softmax --------------------
// One CTA/(b,t). M=128(pad), N=264, K=512. ldmatrix + mma.m16n8k16.bf16,
// cp.async double-buffered B (Wo^T), double-buffered A (tanh built ahead).

#define SMEMB_BYTES 120832
// smem layout (bytes):
#define OFF_FPROW 0        // 512 f32
#define OFF_CCTX  2048     // 112 i32 (pad to 512B)
#define OFF_SA0   2560     // 128 x 72 bf16 = 18432
#define OFF_SA1   20992
#define OFF_SB0   39424    // 264 x 72 bf16 = 38016
#define OFF_SB1   77440    // ends 115456
#define OFF_SLOG  2560     // epilogue union: 112 x 264 f32 = 118272 (ends 120832)

__device__ __forceinline__ void mma16816(
    float c[4], uint32_t a0, uint32_t a1, uint32_t a2, uint32_t a3,
    uint32_t b0, uint32_t b1)
{
    asm volatile(
        "mma.sync.aligned.m16n8k16.row.col.f32.bf16.bf16.f32 "
        "{%0,%1,%2,%3}, {%4,%5,%6,%7}, {%8,%9}, {%0,%1,%2,%3};\n"
        : "+f"(c[0]), "+f"(c[1]), "+f"(c[2]), "+f"(c[3])
        : "r"(a0), "r"(a1), "r"(a2), "r"(a3), "r"(b0), "r"(b1));
}

__device__ __forceinline__ void ldsm_x4(uint32_t& a0, uint32_t& a1,
                                        uint32_t& a2, uint32_t& a3, uint32_t addr)
{
    asm volatile("ldmatrix.sync.aligned.m8n8.x4.shared.b16 {%0,%1,%2,%3}, [%4];"
                 : "=r"(a0), "=r"(a1), "=r"(a2), "=r"(a3) : "r"(addr));
}
__device__ __forceinline__ void ldsm_x2(uint32_t& b0, uint32_t& b1, uint32_t addr)
{
    asm volatile("ldmatrix.sync.aligned.m8n8.x2.shared.b16 {%0,%1}, [%2];"
                 : "=r"(b0), "=r"(b1) : "r"(addr));
}

__global__ __launch_bounds__(512, 1) void joint_kernel(
    const int* __restrict__ labels, const float* __restrict__ E)
{
    extern __shared__ unsigned char smem[];
    float*         fprow = (float*)(smem + OFF_FPROW);
    int*           cctx  = (int*)(smem + OFF_CCTX);
    __nv_bfloat16* sA[2] = { (__nv_bfloat16*)(smem + OFF_SA0),
                             (__nv_bfloat16*)(smem + OFF_SA1) };
    float*         slog  = (float*)(smem + OFF_SLOG);

    const uint32_t smem_u32 = (uint32_t)__cvta_generic_to_shared(smem);
    const uint32_t sAu[2] = { smem_u32 + OFF_SA0, smem_u32 + OFF_SA1 };
    const uint32_t sBu[2] = { smem_u32 + OFF_SB0, smem_u32 + OFF_SB1 };

    const int bt = blockIdx.x;
    const int b  = bt >> 9;
    const int tid = threadIdx.x;
    const int lane = tid & 31, warp = tid >> 5;
    const int gid = lane >> 2, qid = lane & 3;
    const int mg = warp >> 3;        // 0/1 : m-half (4 m-tiles each)
    const int ng = warp & 7;         // 0..7: n-group (4 n-tiles each, ng0 +1)

    // ldmatrix lane address components
    const int a_row = lane & 15;
    const int a_koff = (lane >> 4) * 8;
    const int b_row = lane & 7;
    const int b_koff = ((lane >> 3) & 1) * 8;

    // per-(b,t) header
    fprow[tid & 511] = g_fproj[(size_t)bt * Hh + (tid & 511)];
    if (tid < 112) {
        int u = tid, c = 0;
        if (u >= 1 && u <= Uu) c = labels[b * Uu + (u - 1)];
        cctx[tid] = c;
    }
    __syncthreads();

    // ---- helpers (macros keep register use tight) ----
#define ISSUE_B(kt, buf)                                                      \
    {                                                                         \
        const int k0_ = (kt) * 64;                                            \
        _Pragma("unroll")                                                     \
        for (int i = 0; i < 5; i++) {                                         \
            int idx = tid + i * 512;                                          \
            if (idx < 2112) {                                                 \
                int row = idx >> 3, seg = idx & 7;                            \
                uint32_t dst = sBu[buf] + (uint32_t)(row * 72 + seg * 8) * 2; \
                const __nv_bfloat16* src =                                    \
                    g_WoT + (size_t)row * Hh + k0_ + seg * 8;                 \
                asm volatile("cp.async.cg.shared.global [%0], [%1], 16;\n"    \
                             :: "r"(dst), "l"(src));                          \
            }                                                                 \
        }                                                                     \
        asm volatile("cp.async.commit_group;\n");                            \
    }

#define BUILD_A(kt, buf)                                                      \
    {                                                                         \
        const int k0_ = (kt) * 64;                                            \
        __nv_bfloat16* dA = sA[buf];                                          \
        _Pragma("unroll")                                                     \
        for (int i = 0; i < 8; i++) {                                         \
            int idx = tid + i * 512;                                          \
            int r = idx >> 5, kp = (idx & 31) * 2;                            \
            __nv_bfloat162 h2;                                                \
            if (r < UP1) {                                                    \
                float2 fp = *(const float2*)&fprow[k0_ + kp];                 \
                float2 ev = *(const float2*)&E[(size_t)cctx[r] * Hh + k0_ + kp]; \
                float x0 = fp.x + ev.x, x1 = fp.y + ev.y, t0, t1;             \
                asm("tanh.approx.f32 %0, %1;" : "=f"(t0) : "f"(x0));          \
                asm("tanh.approx.f32 %0, %1;" : "=f"(t1) : "f"(x1));          \
                h2 = __floats2bfloat162_rn(t0, t1);                           \
            } else {                                                          \
                h2 = __floats2bfloat162_rn(0.f, 0.f);                         \
            }                                                                 \
            *reinterpret_cast<__nv_bfloat162*>(&dA[r * 72 + kp]) = h2;        \
        }                                                                     \
    }

    float C[4][5][4];
#pragma unroll
    for (int m = 0; m < 4; m++)
#pragma unroll
        for (int j = 0; j < 5; j++)
#pragma unroll
            for (int q = 0; q < 4; q++) C[m][j][q] = 0.f;

    // prologue
    ISSUE_B(0, 0);
    BUILD_A(0, 0);
    asm volatile("cp.async.wait_group 0;\n");
    __syncthreads();

    for (int kt = 0; kt < 8; kt++) {
        const int cur = kt & 1;
        if (kt < 7) {
            ISSUE_B(kt + 1, cur ^ 1);
            BUILD_A(kt + 1, cur ^ 1);
        }
        // ---- mma on cur ----
        const uint32_t aB = sAu[cur], bB = sBu[cur];
#pragma unroll
        for (int kk = 0; kk < 4; kk++) {
            const int kb = kk * 16;
            uint32_t bf[5][2];
#pragma unroll
            for (int j = 0; j < 4; j++) {
                int nt = ng * 4 + j;
                uint32_t addr = bB + (uint32_t)((nt * 8 + b_row) * 72 + kb + b_koff) * 2;
                ldsm_x2(bf[j][0], bf[j][1], addr);
            }
            if (ng == 0) {
                uint32_t addr = bB + (uint32_t)((32 * 8 + b_row) * 72 + kb + b_koff) * 2;
                ldsm_x2(bf[4][0], bf[4][1], addr);
            }
#pragma unroll
            for (int mti = 0; mti < 4; mti++) {
                const int mtg = mg * 4 + mti;
                uint32_t a0, a1, a2, a3;
                uint32_t addr = aB + (uint32_t)((mtg * 16 + a_row) * 72 + kb + a_koff) * 2;
                ldsm_x4(a0, a1, a2, a3, addr);
#pragma unroll
                for (int j = 0; j < 4; j++)
                    mma16816(C[mti][j], a0, a1, a2, a3, bf[j][0], bf[j][1]);
                if (ng == 0)
                    mma16816(C[mti][4], a0, a1, a2, a3, bf[4][0], bf[4][1]);
            }
        }
        if (kt < 7) asm volatile("cp.async.wait_group 0;\n");
        __syncthreads();
    }

    // ---- epilogue: registers -> smem logits ----
#pragma unroll
    for (int mti = 0; mti < 4; mti++) {
        const int mtg = mg * 4 + mti;
        if (mtg >= 7) continue;            // rows 112..127 are padding
        const int r = mtg * 16 + gid;
#pragma unroll
        for (int j = 0; j < 4; j++) {
            int c = (ng * 4 + j) * 8 + qid * 2;
            *(float2*)&slog[r * NPAD + c]       = make_float2(C[mti][j][0], C[mti][j][1]);
            *(float2*)&slog[(r + 8) * NPAD + c] = make_float2(C[mti][j][2], C[mti][j][3]);
        }
        if (ng == 0) {
            int c = 32 * 8 + qid * 2;
            *(float2*)&slog[r * NPAD + c]       = make_float2(C[mti][4][0], C[mti][4][1]);
            *(float2*)&slog[(r + 8) * NPAD + c] = make_float2(C[mti][4][2], C[mti][4][3]);
        }
    }
    __syncthreads();

    // ---- per-row LSE (logits tiny, no max-shift needed) ----
    for (int r = warp; r < UP1; r += 16) {
        float s = 0.f;
        for (int c = lane; c < VP1; c += 32)
            s += __expf(slog[r * NPAD + c]);
#pragma unroll
        for (int o = 16; o; o >>= 1) s += __shfl_xor_sync(0xffffffffu, s, o);
        float lse = __logf(s);
        if (lane == 0) {
            g_blank[(size_t)bt * UP1 + r] = slog[r * NPAD] - lse;
            if (r < Uu) {
                int lab = labels[b * Uu + r];
                g_lex[(size_t)bt * Uu + r] = slog[r * NPAD + lab] - lse;
            }
        }
    }
#undef ISSUE_B
#undef BUILD_A
}

// ---------------- kernel 4: forward DP, single warp per batch ------------
__global__ __launch_bounds__(32) void dp_kernel(
    const int* __restrict__ num_frames, const int* __restrict__ num_labels,
    float* __restrict__ out)
{
    const int lane = threadIdx.x;
    const int b = blockIdx.x;
    const int nf = num_frames[b];
    const int nl = num_labels[b];
    const unsigned FULL = 0xffffffffu;

    const float* bl_ptr = g_blank + (size_t)b * Tt * UP1;
    const float* lx_ptr = g_lex + (size_t)b * Tt * Uu;

    float al[4];
#pragma unroll
    for (int i = 0; i < 4; i++) {
        int u = lane + 32 * i;
        al[i] = (u == 0) ? 0.f : NEG_INFF;
    }

    float bl[4], lx[4], bln[4], lxn[4];
#pragma unroll
    for (int i = 0; i < 4; i++) {
        int u = lane + 32 * i;
        bl[i] = (u < UP1) ? bl_ptr[u] : NEG_INFF;
        lx[i] = (u >= 1 && u <= Uu) ? lx_ptr[u - 1] : NEG_INFF;
    }

    for (int t = 0; t < Tt; t++) {
        // prefetch t+1
        if (t + 1 < Tt) {
#pragma unroll
            for (int i = 0; i < 4; i++) {
                int u = lane + 32 * i;
                bln[i] = (u < UP1) ? bl_ptr[(t + 1) * UP1 + u] : NEG_INFF;
                lxn[i] = (u >= 1 && u <= Uu) ? lx_ptr[(t + 1) * Uu + u - 1] : NEG_INFF;
            }
        }
        float pt[4];
        pt[0] = NEG_INFF;
#pragma unroll
        for (int i = 1; i < 4; i++) pt[i] = __shfl_sync(FULL, al[i - 1], 31);
        const bool keep = (t < nf);
#pragma unroll
        for (int i = 0; i < 4; i++) {
            float sh = __shfl_up_sync(FULL, al[i], 1);
            if (lane == 0) sh = pt[i];
            float stay = al[i] + bl[i];
            float emit = sh + lx[i];
            float m = fmaxf(stay, emit);
            float d = fminf(stay, emit) - m;
            float nv = m + __logf(1.0f + __expf(d));
            if (m < -1e29f) nv = NEG_INFF;
            if (keep) al[i] = nv;
        }
#pragma unroll
        for (int i = 0; i < 4; i++) { bl[i] = bln[i]; lx[i] = lxn[i]; }
    }

    const int ci = nl >> 5, li = nl & 31;
    float v = al[0];
    if (ci == 1) v = al[1];
    else if (ci == 2) v = al[2];
    else if (ci == 3) v = al[3];
    float r = __shfl_sync(FULL, v, li);
    if (lane == 0) out[b] = -r;
}

// ---------------- launch ------------------------------------------------
extern "C" void kernel_launch(void* const* d_in, const int* in_sizes, int n_in,
                              void* d_out, int out_size)
{
    const float* frames     = (const float*)d_in[0];
    const int*   num_frames = (const int*)  d_in[1];
    const int*   labels     = (const int*)  d_in[2];
    const int*   num_labels = (const int*)  d_in[3];
    const float* Wf         = (const float*)d_in[4];
    const float* E          = (const float*)d_in[5];
    const float* Wo         = (const float*)d_in[6];
    float* out = (float*)d_out;

    cudaFuncSetAttribute(joint_kernel,
                         cudaFuncAttributeMaxDynamicSharedMemorySize, SMEMB_BYTES);

    fproj_kernel<<<dim3(Bb * Tt / 64, Hh / 64), 256>>>(frames, Wf);
    woprep_kernel<<<(Hh * VP1 + 255) / 256, 256>>>(Wo);
    joint_kernel<<<Bb * Tt, 512, SMEMB_BYTES>>>(labels, E);
    dp_kernel<<<Bb, 32>>>(num_frames, num_labels, out);
}

// round 7
// speedup vs baseline: 1.5458x; 1.1480x over previous
#include <cuda_runtime.h>
#include <cuda_bf16.h>
#include <cstdint>

// Problem constants
#define Bb   4
#define Tt   512
#define Uu   96
#define Ff   512
#define Hh   512
#define Vv   256
#define UP1  97      // U+1 lattice rows
#define VP1  257     // V+1 vocab (incl. blank)
#define NPAD 264     // VP1 padded to 33 n-tiles of 8
#define MPAD 128     // 112 rows padded to 8 m-tiles of 16
#define NEG_INFF (-1e30f)

// ---------------- device scratch ----------------
__device__ float          g_fproj[Bb * Tt * Hh];     // 4 MB
__device__ __nv_bfloat16  g_WoT[NPAD * Hh];          // Wo transposed: [n][k]
__device__ float          g_blank[Bb * Tt * UP1];
__device__ float          g_lex[Bb * Tt * Uu];

// ---------------- kernel 1: fproj = frames @ Wf (fp32 tiled) -------------
__global__ __launch_bounds__(256) void fproj_kernel(
    const float* __restrict__ frames, const float* __restrict__ Wf)
{
    __shared__ float sF[64][36];
    __shared__ float sW[32][68];
    const int row0 = blockIdx.x * 64;
    const int col0 = blockIdx.y * 64;
    const int tid = threadIdx.x;
    const int tx = tid & 15, ty = tid >> 4;

    float acc[4][4];
#pragma unroll
    for (int i = 0; i < 4; i++)
#pragma unroll
        for (int j = 0; j < 4; j++) acc[i][j] = 0.f;

    for (int k0 = 0; k0 < Ff; k0 += 32) {
        __syncthreads();
#pragma unroll
        for (int i = 0; i < 8; i++) {
            int idx = tid + i * 256;
            int r = idx >> 5, k = idx & 31;
            sF[r][k] = frames[(size_t)(row0 + r) * Ff + k0 + k];
        }
#pragma unroll
        for (int i = 0; i < 8; i++) {
            int idx = tid + i * 256;
            int k = idx >> 6, c = idx & 63;
            sW[k][c] = Wf[(size_t)(k0 + k) * Hh + col0 + c];
        }
        __syncthreads();
#pragma unroll
        for (int k = 0; k < 32; k++) {
            float a_[4], b_[4];
#pragma unroll
            for (int i = 0; i < 4; i++) a_[i] = sF[ty * 4 + i][k];
#pragma unroll
            for (int j = 0; j < 4; j++) b_[j] = sW[k][tx * 4 + j];
#pragma unroll
            for (int i = 0; i < 4; i++)
#pragma unroll
                for (int j = 0; j < 4; j++) acc[i][j] += a_[i] * b_[j];
        }
    }
#pragma unroll
    for (int i = 0; i < 4; i++)
#pragma unroll
        for (int j = 0; j < 4; j++)
            g_fproj[(size_t)(row0 + ty * 4 + i) * Hh + col0 + tx * 4 + j] = acc[i][j];
}

// ---------------- kernel 2: Wo -> bf16 transposed [n][k] ------------------
__global__ void woprep_kernel(const float* __restrict__ Wo)
{
    int i = blockIdx.x * blockDim.x + threadIdx.x;
    if (i < Hh * VP1) {
        int k = i / VP1, n = i - k * VP1;   // coalesced read of Wo
        g_WoT[(size_t)n * Hh + k] = __float2bfloat16(Wo[i]);
    }
    if (i < (NPAD - VP1) * Hh) {            // zero-pad rows 257..263
        int n = VP1 + i / Hh, k = i - (i / Hh) * Hh;
        g_WoT[(size_t)n * Hh + k] = __float2bfloat16(0.f);
    }
}

// ---------------- kernel 3: fused joint + log-softmax --------------------
// One CTA/(b,t). M=128(pad), N=264, K=512. ldmatrix + mma.m16n8k16.bf16,
// cp.async double-buffered B (Wo^T), double-buffered A (tanh built ahead).

#define SMEMB_BYTES 120832
// smem layout (bytes):
#define OFF_FPROW 0        // 512 f32
#define OFF_CCTX  2048     // 112 i32 (pad to 512B)
#define OFF_SA0   2560     // 128 x 72 bf16 = 18432
#define OFF_SA1   20992
#define OFF_SB0   39424    // 264 x 72 bf16 = 38016
#define OFF_SB1   77440    // ends 115456
#define OFF_SLOG  2560     // epilogue union: 112 x 264 f32 = 118272 (ends 120832)

__device__ __forceinline__ void mma16816(
    float c[4], uint32_t a0, uint32_t a1, uint32_t a2, uint32_t a3,
    uint32_t b0, uint32_t b1)
{
    asm volatile(
        "mma.sync.aligned.m16n8k16.row.col.f32.bf16.bf16.f32 "
        "{%0,%1,%2,%3}, {%4,%5,%6,%7}, {%8,%9}, {%0,%1,%2,%3};\n"
        : "+f"(c[0]), "+f"(c[1]), "+f"(c[2]), "+f"(c[3])
        : "r"(a0), "r"(a1), "r"(a2), "r"(a3), "r"(b0), "r"(b1));
}

__device__ __forceinline__ void ldsm_x4(uint32_t& a0, uint32_t& a1,
                                        uint32_t& a2, uint32_t& a3, uint32_t addr)
{
    asm volatile("ldmatrix.sync.aligned.m8n8.x4.shared.b16 {%0,%1,%2,%3}, [%4];"
                 : "=r"(a0), "=r"(a1), "=r"(a2), "=r"(a3) : "r"(addr));
}
__device__ __forceinline__ void ldsm_x2(uint32_t& b0, uint32_t& b1, uint32_t addr)
{
    asm volatile("ldmatrix.sync.aligned.m8n8.x2.shared.b16 {%0,%1}, [%2];"
                 : "=r"(b0), "=r"(b1) : "r"(addr));
}

__global__ __launch_bounds__(512, 1) void joint_kernel(
    const int* __restrict__ labels, const float* __restrict__ E)
{
    extern __shared__ unsigned char smem[];
    float*         fprow = (float*)(smem + OFF_FPROW);
    int*           cctx  = (int*)(smem + OFF_CCTX);
    __nv_bfloat16* sA[2] = { (__nv_bfloat16*)(smem + OFF_SA0),
                             (__nv_bfloat16*)(smem + OFF_SA1) };
    float*         slog  = (float*)(smem + OFF_SLOG);

    const uint32_t smem_u32 = (uint32_t)__cvta_generic_to_shared(smem);
    const uint32_t sAu[2] = { smem_u32 + OFF_SA0, smem_u32 + OFF_SA1 };
    const uint32_t sBu[2] = { smem_u32 + OFF_SB0, smem_u32 + OFF_SB1 };

    const int bt = blockIdx.x;
    const int b  = bt >> 9;
    const int tid = threadIdx.x;
    const int lane = tid & 31, warp = tid >> 5;
    const int gid = lane >> 2, qid = lane & 3;
    const int mg = warp >> 3;        // 0/1 : m-half (4 m-tiles each)
    const int ng = warp & 7;         // 0..7: n-group (4 n-tiles each, ng0 +1)

    // ldmatrix lane address components
    const int a_row = lane & 15;
    const int a_koff = (lane >> 4) * 8;
    const int b_row = lane & 7;
    const int b_koff = ((lane >> 3) & 1) * 8;

    // per-(b,t) header
    fprow[tid & 511] = g_fproj[(size_t)bt * Hh + (tid & 511)];
    if (tid < 112) {
        int u = tid, c = 0;
        if (u >= 1 && u <= Uu) c = labels[b * Uu + (u - 1)];
        cctx[tid] = c;
    }
    __syncthreads();

    // ---- helpers (macros keep register use tight) ----
#define ISSUE_B(kt, buf)                                                      \
    {                                                                         \
        const int k0_ = (kt) * 64;                                            \
        _Pragma("unroll")                                                     \
        for (int i = 0; i < 5; i++) {                                         \
            int idx = tid + i * 512;                                          \
            if (idx < 2112) {                                                 \
                int row = idx >> 3, seg = idx & 7;                            \
                uint32_t dst = sBu[buf] + (uint32_t)(row * 72 + seg * 8) * 2; \
                const __nv_bfloat16* src =                                    \
                    g_WoT + (size_t)row * Hh + k0_ + seg * 8;                 \
                asm volatile("cp.async.cg.shared.global [%0], [%1], 16;\n"    \
                             :: "r"(dst), "l"(src));                          \
            }                                                                 \
        }                                                                     \
        asm volatile("cp.async.commit_group;\n");                            \
    }

#define BUILD_A(kt, buf)                                                      \
    {                                                                         \
        const int k0_ = (kt) * 64;                                            \
        __nv_bfloat16* dA = sA[buf];                                          \
        _Pragma("unroll")                                                     \
        for (int i = 0; i < 8; i++) {                                         \
            int idx = tid + i * 512;                                          \
            int r = idx >> 5, kp = (idx & 31) * 2;                            \
            __nv_bfloat162 h2;                                                \
            if (r < UP1) {                                                    \
                float2 fp = *(const float2*)&fprow[k0_ + kp];                 \
                float2 ev = *(const float2*)&E[(size_t)cctx[r] * Hh + k0_ + kp]; \
                float x0 = fp.x + ev.x, x1 = fp.y + ev.y, t0, t1;             \
                asm("tanh.approx.f32 %0, %1;" : "=f"(t0) : "f"(x0));          \
                asm("tanh.approx.f32 %0, %1;" : "=f"(t1) : "f"(x1));          \
                h2 = __floats2bfloat162_rn(t0, t1);                           \
            } else {                                                          \
                h2 = __floats2bfloat162_rn(0.f, 0.f);                         \
            }                                                                 \
            *reinterpret_cast<__nv_bfloat162*>(&dA[r * 72 + kp]) = h2;        \
        }                                                                     \
    }

    float C[4][5][4];
#pragma unroll
    for (int m = 0; m < 4; m++)
#pragma unroll
        for (int j = 0; j < 5; j++)
#pragma unroll
            for (int q = 0; q < 4; q++) C[m][j][q] = 0.f;

    // prologue
    ISSUE_B(0, 0);
    BUILD_A(0, 0);
    asm volatile("cp.async.wait_group 0;\n");
    __syncthreads();

    for (int kt = 0; kt < 8; kt++) {
        const int cur = kt & 1;
        if (kt < 7) {
            ISSUE_B(kt + 1, cur ^ 1);
            BUILD_A(kt + 1, cur ^ 1);
        }
        // ---- mma on cur ----
        const uint32_t aB = sAu[cur], bB = sBu[cur];
#pragma unroll
        for (int kk = 0; kk < 4; kk++) {
            const int kb = kk * 16;
            uint32_t bf[5][2];
#pragma unroll
            for (int j = 0; j < 4; j++) {
                int nt = ng * 4 + j;
                uint32_t addr = bB + (uint32_t)((nt * 8 + b_row) * 72 + kb + b_koff) * 2;
                ldsm_x2(bf[j][0], bf[j][1], addr);
            }
            if (ng == 0) {
                uint32_t addr = bB + (uint32_t)((32 * 8 + b_row) * 72 + kb + b_koff) * 2;
                ldsm_x2(bf[4][0], bf[4][1], addr);
            }
#pragma unroll
            for (int mti = 0; mti < 4; mti++) {
                const int mtg = mg * 4 + mti;
                uint32_t a0, a1, a2, a3;
                uint32_t addr = aB + (uint32_t)((mtg * 16 + a_row) * 72 + kb + a_koff) * 2;
                ldsm_x4(a0, a1, a2, a3, addr);
#pragma unroll
                for (int j = 0; j < 4; j++)
                    mma16816(C[mti][j], a0, a1, a2, a3, bf[j][0], bf[j][1]);
                if (ng == 0)
                    mma16816(C[mti][4], a0, a1, a2, a3, bf[4][0], bf[4][1]);
            }
        }
        if (kt < 7) asm volatile("cp.async.wait_group 0;\n");
        __syncthreads();
    }

    // ---- epilogue: registers -> smem logits ----
#pragma unroll
    for (int mti = 0; mti < 4; mti++) {
        const int mtg = mg * 4 + mti;
        if (mtg >= 7) continue;            // rows 112..127 are padding
        const int r = mtg * 16 + gid;
#pragma unroll
        for (int j = 0; j < 4; j++) {
            int c = (ng * 4 + j) * 8 + qid * 2;
            *(float2*)&slog[r * NPAD + c]       = make_float2(C[mti][j][0], C[mti][j][1]);
            *(float2*)&slog[(r + 8) * NPAD + c] = make_float2(C[mti][j][2], C[mti][j][3]);
        }
        if (ng == 0) {
            int c = 32 * 8 + qid * 2;
            *(float2*)&slog[r * NPAD + c]       = make_float2(C[mti][4][0], C[mti][4][1]);
            *(float2*)&slog[(r + 8) * NPAD + c] = make_float2(C[mti][4][2], C[mti][4][3]);
        }
    }
    __syncthreads();

    // ---- per-row LSE (logits tiny, no max-shift needed) ----
    for (int r = warp; r < UP1; r += 16) {
        float s = 0.f;
        for (int c = lane; c < VP1; c += 32)
            s += __expf(slog[r * NPAD + c]);
#pragma unroll
        for (int o = 16; o; o >>= 1) s += __shfl_xor_sync(0xffffffffu, s, o);
        float lse = __logf(s);
        if (lane == 0) {
            g_blank[(size_t)bt * UP1 + r] = slog[r * NPAD] - lse;
            if (r < Uu) {
                int lab = labels[b * Uu + r];
                g_lex[(size_t)bt * Uu + r] = slog[r * NPAD + lab] - lse;
            }
        }
    }
#undef ISSUE_B
#undef BUILD_A
}

// ---------------- kernel 4: forward DP, single warp per batch ------------
// 4-deep software pipeline: loads for step t+4 issue before the MUFU chain
// of step t, fully hiding L2 latency (~250 cyc) behind 4 steps of compute.
__global__ __launch_bounds__(32) void dp_kernel(
    const int* __restrict__ num_frames, const int* __restrict__ num_labels,
    float* __restrict__ out)
{
    const int lane = threadIdx.x;
    const int b = blockIdx.x;
    const int nf = num_frames[b];
    const int nl = num_labels[b];
    const unsigned FULL = 0xffffffffu;

    const float* bl_ptr = g_blank + (size_t)b * Tt * UP1;
    const float* lx_ptr = g_lex + (size_t)b * Tt * Uu;

    float al[4];
#pragma unroll
    for (int i = 0; i < 4; i++) {
        int u = lane + 32 * i;
        al[i] = (u == 0) ? 0.f : NEG_INFF;
    }

    // 4-slot register ring of arc weights
    float blb[4][4], lxb[4][4];
#pragma unroll
    for (int s = 0; s < 4; s++)
#pragma unroll
        for (int i = 0; i < 4; i++) {
            int u = lane + 32 * i;
            blb[s][i] = (u < UP1) ? bl_ptr[s * UP1 + u] : NEG_INFF;
            lxb[s][i] = (u >= 1 && u <= Uu) ? lx_ptr[s * Uu + u - 1] : NEG_INFF;
        }

    for (int t0 = 0; t0 < Tt; t0 += 4) {
#pragma unroll
        for (int s = 0; s < 4; s++) {
            const int t = t0 + s;
            // consume current slot into locals
            float bl[4], lx[4];
#pragma unroll
            for (int i = 0; i < 4; i++) { bl[i] = blb[s][i]; lx[i] = lxb[s][i]; }
            // prefetch t+4 into this slot (issues before the MUFU chain)
            const int tp = t + 4;
            if (tp < Tt) {
#pragma unroll
                for (int i = 0; i < 4; i++) {
                    int u = lane + 32 * i;
                    blb[s][i] = (u < UP1) ? bl_ptr[(size_t)tp * UP1 + u] : NEG_INFF;
                    lxb[s][i] = (u >= 1 && u <= Uu) ? lx_ptr[(size_t)tp * Uu + u - 1]
                                                    : NEG_INFF;
                }
            }
            // lattice step
            float pt[4];
            pt[0] = NEG_INFF;
#pragma unroll
            for (int i = 1; i < 4; i++) pt[i] = __shfl_sync(FULL, al[i - 1], 31);
            const bool keep = (t < nf);
#pragma unroll
            for (int i = 0; i < 4; i++) {
                float sh = __shfl_up_sync(FULL, al[i], 1);
                if (lane == 0) sh = pt[i];
                float stay = al[i] + bl[i];
                float emit = sh + lx[i];
                float m = fmaxf(stay, emit);
                float d = fminf(stay, emit) - m;
                float nv = m + __logf(1.0f + __expf(d));
                if (m < -1e29f) nv = NEG_INFF;
                if (keep) al[i] = nv;
            }
        }
    }

    const int ci = nl >> 5, li = nl & 31;
    float v = al[0];
    if (ci == 1) v = al[1];
    else if (ci == 2) v = al[2];
    else if (ci == 3) v = al[3];
    float r = __shfl_sync(FULL, v, li);
    if (lane == 0) out[b] = -r;
}

// ---------------- launch ------------------------------------------------
extern "C" void kernel_launch(void* const* d_in, const int* in_sizes, int n_in,
                              void* d_out, int out_size)
{
    const float* frames     = (const float*)d_in[0];
    const int*   num_frames = (const int*)  d_in[1];
    const int*   labels     = (const int*)  d_in[2];
    const int*   num_labels = (const int*)  d_in[3];
    const float* Wf         = (const float*)d_in[4];
    const float* E          = (const float*)d_in[5];
    const float* Wo         = (const float*)d_in[6];
    float* out = (float*)d_out;

    cudaFuncSetAttribute(joint_kernel,
                         cudaFuncAttributeMaxDynamicSharedMemorySize, SMEMB_BYTES);

    fproj_kernel<<<dim3(Bb * Tt / 64, Hh / 64), 256>>>(frames, Wf);
    woprep_kernel<<<(Hh * VP1 + 255) / 256, 256>>>(Wo);
    joint_kernel<<<Bb * Tt, 512, SMEMB_BYTES>>>(labels, E);
    dp_kernel<<<Bb, 32>>>(num_frames, num_labels, out);
}